// round 1
// baseline (speedup 1.0000x reference)
#include <cuda_runtime.h>
#include <math.h>

#define D_MODEL 1024
#define D_INNER 2048
#define D_STATE 16
#define D_CONV  4
#define DT_RANK 64
#define BATCH   2
#define SEQLEN  1024
#define BL      (BATCH * SEQLEN)          // 2048 rows
#define XPROJ   (DT_RANK + 2 * D_STATE)   // 96
#define KSPLIT  8

// ---------------- scratch (static device globals; no allocs allowed) -------
__device__ __align__(16) float g_xz[(size_t)BL * 2 * D_INNER];   // 32 MB
__device__ __align__(16) float g_xc[(size_t)BL * D_INNER];       // 16 MB
__device__ __align__(16) float g_xdbl[(size_t)BL * XPROJ];
__device__ __align__(16) float g_part[(size_t)KSPLIT * BL * XPROJ];
__device__ __align__(16) float g_delta[(size_t)BL * D_INNER];    // 16 MB
__device__ __align__(16) float g_y[(size_t)BL * D_INNER];        // 16 MB

// ---------------- SGEMM: C[M,N] = A[M,K] * B[N,K]^T  (both row-major) ------
// 128x128 block tile, BK=8, 256 threads, 8x8 per-thread micro-tile.
// gridDim.z = K-split count (K divisible); each z writes its own C slab.
// EPI: 0 = plain store, 1 = add bias[n] then softplus.
template <int EPI>
__global__ __launch_bounds__(256)
void sgemm_tn(const float* __restrict__ A, int lda,
              const float* __restrict__ B, int ldb,
              float* __restrict__ C, int ldc,
              int M, int N, int K,
              const float* __restrict__ bias)
{
    __shared__ float As[8][128];
    __shared__ float Bs[8][128];

    const int tid  = threadIdx.x;
    const int row0 = blockIdx.y * 128;
    const int col0 = blockIdx.x * 128;
    const int kc   = K / gridDim.z;
    const int kBeg = blockIdx.z * kc;
    const int kEnd = kBeg + kc;
    float* Cc = C + (size_t)blockIdx.z * (size_t)M * (size_t)ldc;

    const int ldRow = tid >> 1;          // 0..127
    const int ldK   = (tid & 1) * 4;     // 0 or 4
    const float* Aload = A + (size_t)(row0 + ldRow) * lda + ldK;
    const bool   bValid = (col0 + ldRow) < N;
    const float* Bload = B + (size_t)(col0 + ldRow) * ldb + ldK;

    const int tx = tid & 15;             // 0..15 -> n
    const int ty = tid >> 4;             // 0..15 -> m

    float acc[8][8];
#pragma unroll
    for (int i = 0; i < 8; i++)
#pragma unroll
        for (int j = 0; j < 8; j++) acc[i][j] = 0.f;

    for (int k0 = kBeg; k0 < kEnd; k0 += 8) {
        float4 av = *(const float4*)(Aload + k0);
        float4 bv = make_float4(0.f, 0.f, 0.f, 0.f);
        if (bValid) bv = *(const float4*)(Bload + k0);

        As[ldK + 0][ldRow] = av.x;
        As[ldK + 1][ldRow] = av.y;
        As[ldK + 2][ldRow] = av.z;
        As[ldK + 3][ldRow] = av.w;
        Bs[ldK + 0][ldRow] = bv.x;
        Bs[ldK + 1][ldRow] = bv.y;
        Bs[ldK + 2][ldRow] = bv.z;
        Bs[ldK + 3][ldRow] = bv.w;
        __syncthreads();

#pragma unroll
        for (int kk = 0; kk < 8; kk++) {
            float4 a0 = *(const float4*)&As[kk][ty * 8];
            float4 a1 = *(const float4*)&As[kk][ty * 8 + 4];
            float4 b0 = *(const float4*)&Bs[kk][tx * 8];
            float4 b1 = *(const float4*)&Bs[kk][tx * 8 + 4];
            float a[8] = {a0.x, a0.y, a0.z, a0.w, a1.x, a1.y, a1.z, a1.w};
            float b[8] = {b0.x, b0.y, b0.z, b0.w, b1.x, b1.y, b1.z, b1.w};
#pragma unroll
            for (int i = 0; i < 8; i++)
#pragma unroll
                for (int j = 0; j < 8; j++)
                    acc[i][j] = fmaf(a[i], b[j], acc[i][j]);
        }
        __syncthreads();
    }

#pragma unroll
    for (int i = 0; i < 8; i++) {
        int r = row0 + ty * 8 + i;
#pragma unroll
        for (int j = 0; j < 8; j++) {
            int c = col0 + tx * 8 + j;
            if (c < N) {
                float v = acc[i][j];
                if (EPI == 1) {
                    v += bias[c];
                    v = (v > 20.f) ? v : log1pf(expf(v));  // softplus
                }
                Cc[(size_t)r * ldc + c] = v;
            }
        }
    }
}

// ---------------- reduce split-K partials for x_proj -----------------------
__global__ void reduce_part_kernel()
{
    int i = blockIdx.x * blockDim.x + threadIdx.x;
    if (i < BL * XPROJ) {
        float s = 0.f;
#pragma unroll
        for (int p = 0; p < KSPLIT; p++)
            s += g_part[(size_t)p * BL * XPROJ + i];
        g_xdbl[i] = s;
    }
}

// ---------------- depthwise causal conv (D_CONV=4) + bias + SiLU -----------
__global__ void conv_silu_kernel(const float* __restrict__ w,
                                 const float* __restrict__ bias)
{
    int idx = blockIdx.x * blockDim.x + threadIdx.x;
    if (idx >= BL * D_INNER) return;
    int d  = idx % D_INNER;
    int bl = idx / D_INNER;
    int l  = bl % SEQLEN;

    float acc = bias[d];
#pragma unroll
    for (int k = 0; k < D_CONV; k++) {
        int lk = l - (D_CONV - 1) + k;
        if (lk >= 0)
            acc += w[d * D_CONV + k] *
                   g_xz[(size_t)(bl - (D_CONV - 1 - k)) * (2 * D_INNER) + d];
    }
    float sg = 1.f / (1.f + expf(-acc));
    g_xc[idx] = acc * sg;
}

// ---------------- selective scan + gating ----------------------------------
// grid: (D_INNER/16, BATCH); block 256 = 16 channels x 16 states.
// Thread (dc, n): maintains state s for channel d0+dc, state index n.
// y_t = sum_n s_n * C_t[n]  via 4x shfl.xor within 16-lane groups.
__global__ __launch_bounds__(256)
void scan_kernel(const float* __restrict__ A_log,
                 const float* __restrict__ D_skip)
{
    const int TL = 64;
    __shared__ float sDelta[TL][16];
    __shared__ float sU[TL][16];
    __shared__ float sB[TL][16];
    __shared__ float sC[TL][16];
    __shared__ float sY[TL][16];

    const int b   = blockIdx.y;
    const int d0  = blockIdx.x * 16;
    const int tid = threadIdx.x;
    const int dc  = tid >> 4;   // channel within block (0..15)
    const int n   = tid & 15;   // state index (0..15)
    const int d   = d0 + dc;

    const float An = -expf(A_log[d * D_STATE + n]);
    float s = 0.f;

    for (int l0 = 0; l0 < SEQLEN; l0 += TL) {
        // cooperative stage-in
        for (int i = tid; i < TL * 16; i += 256) {
            int t = i >> 4, c = i & 15;
            size_t row = (size_t)(b * SEQLEN + l0 + t);
            sDelta[t][c] = g_delta[row * D_INNER + d0 + c];
            sU[t][c]     = g_xc[row * D_INNER + d0 + c];
            sB[t][c]     = g_xdbl[row * XPROJ + DT_RANK + c];
            sC[t][c]     = g_xdbl[row * XPROJ + DT_RANK + D_STATE + c];
        }
        __syncthreads();

        for (int t = 0; t < TL; t++) {
            float dl = sDelta[t][dc];
            float dA = __expf(dl * An);
            s = fmaf(s, dA, (dl * sU[t][dc]) * sB[t][n]);
            float v = s * sC[t][n];
            v += __shfl_xor_sync(0xffffffffu, v, 8);
            v += __shfl_xor_sync(0xffffffffu, v, 4);
            v += __shfl_xor_sync(0xffffffffu, v, 2);
            v += __shfl_xor_sync(0xffffffffu, v, 1);
            if (n == 0) sY[t][dc] = v;
        }
        __syncthreads();

        // fused epilogue: (y + u*D) * silu(z)
        for (int i = tid; i < TL * 16; i += 256) {
            int t = i >> 4, c = i & 15;
            size_t row = (size_t)(b * SEQLEN + l0 + t);
            float u  = sU[t][c];
            float yv = sY[t][c] + u * D_skip[d0 + c];
            float z  = g_xz[row * (2 * D_INNER) + D_INNER + d0 + c];
            yv *= z / (1.f + expf(-z));
            g_y[row * D_INNER + d0 + c] = yv;
        }
        __syncthreads();
    }
}

// ---------------- launcher --------------------------------------------------
extern "C" void kernel_launch(void* const* d_in, const int* in_sizes, int n_in,
                              void* d_out, int out_size)
{
    const float* hidden     = (const float*)d_in[0];
    const float* in_proj_w  = (const float*)d_in[1];
    const float* conv_w     = (const float*)d_in[2];
    const float* conv_b     = (const float*)d_in[3];
    const float* x_proj_w   = (const float*)d_in[4];
    const float* dt_proj_w  = (const float*)d_in[5];
    const float* dt_proj_b  = (const float*)d_in[6];
    const float* A_log      = (const float*)d_in[7];
    const float* D_skip     = (const float*)d_in[8];
    const float* out_proj_w = (const float*)d_in[9];
    float* out = (float*)d_out;

    float *xz, *xc, *xdbl, *part, *delta, *y;
    cudaGetSymbolAddress((void**)&xz,    g_xz);
    cudaGetSymbolAddress((void**)&xc,    g_xc);
    cudaGetSymbolAddress((void**)&xdbl,  g_xdbl);
    cudaGetSymbolAddress((void**)&part,  g_part);
    cudaGetSymbolAddress((void**)&delta, g_delta);
    cudaGetSymbolAddress((void**)&y,     g_y);

    // 1) xz = hidden @ in_proj_w^T   (2048 x 4096 x 1024)
    sgemm_tn<0><<<dim3(4096 / 128, BL / 128, 1), 256>>>(
        hidden, D_MODEL, in_proj_w, D_MODEL, xz, 2 * D_INNER,
        BL, 2 * D_INNER, D_MODEL, nullptr);

    // 2) depthwise conv + SiLU -> xc
    conv_silu_kernel<<<(BL * D_INNER + 255) / 256, 256>>>(conv_w, conv_b);

    // 3) x_dbl = xc @ x_proj_w^T    (2048 x 96 x 2048), split-K=8 + reduce
    sgemm_tn<0><<<dim3(1, BL / 128, KSPLIT), 256>>>(
        xc, D_INNER, x_proj_w, D_INNER, part, XPROJ,
        BL, XPROJ, D_INNER, nullptr);
    reduce_part_kernel<<<(BL * XPROJ + 255) / 256, 256>>>();

    // 4) delta = softplus(dt_lr @ dt_proj_w^T + dt_b)  (2048 x 2048 x 64)
    sgemm_tn<1><<<dim3(D_INNER / 128, BL / 128, 1), 256>>>(
        xdbl, XPROJ, dt_proj_w, DT_RANK, delta, D_INNER,
        BL, D_INNER, DT_RANK, dt_proj_b);

    // 5) selective scan + gating -> y
    scan_kernel<<<dim3(D_INNER / 16, BATCH), 256>>>(A_log, D_skip);

    // 6) out = y @ out_proj_w^T     (2048 x 1024 x 2048)
    sgemm_tn<0><<<dim3(D_MODEL / 128, BL / 128, 1), 256>>>(
        y, D_INNER, out_proj_w, D_INNER, out, D_MODEL,
        BL, D_MODEL, D_INNER, nullptr);
}

// round 3
// speedup vs baseline: 2.2993x; 2.2993x over previous
#include <cuda_runtime.h>
#include <cuda_bf16.h>
#include <math.h>
#include <stdint.h>

#define D_MODEL 1024
#define D_INNER 2048
#define D_STATE 16
#define D_CONV  4
#define DT_RANK 64
#define BATCH   2
#define SEQLEN  1024
#define BL      (BATCH * SEQLEN)          // 2048 rows
#define XPROJ   (DT_RANK + 2 * D_STATE)   // 96
#define KSPLIT  8

typedef __nv_bfloat16 bf16;

// ---------------- scratch (static device globals; no allocs allowed) -------
__device__ __align__(16) float g_xz  [(size_t)BL * 2 * D_INNER];   // 32 MB
__device__ __align__(16) float g_xc  [(size_t)BL * D_INNER];       // 16 MB
__device__ __align__(16) bf16  g_xch [(size_t)BL * D_INNER];
__device__ __align__(16) bf16  g_xcl [(size_t)BL * D_INNER];
__device__ __align__(16) float g_xdbl[(size_t)BL * XPROJ];
__device__ __align__(16) float g_part[(size_t)KSPLIT * BL * XPROJ];
__device__ __align__(16) bf16  g_dth [(size_t)BL * DT_RANK];
__device__ __align__(16) bf16  g_dtl [(size_t)BL * DT_RANK];
__device__ __align__(16) float g_delta[(size_t)BL * D_INNER];      // 16 MB
__device__ __align__(16) bf16  g_yh  [(size_t)BL * D_INNER];
__device__ __align__(16) bf16  g_yl  [(size_t)BL * D_INNER];
__device__ __align__(16) bf16  g_hh  [(size_t)BL * D_MODEL];
__device__ __align__(16) bf16  g_hl  [(size_t)BL * D_MODEL];
__device__ __align__(16) bf16  g_w1h [(size_t)2 * D_INNER * D_MODEL];
__device__ __align__(16) bf16  g_w1l [(size_t)2 * D_INNER * D_MODEL];
__device__ __align__(16) bf16  g_w3h [(size_t)XPROJ * D_INNER];
__device__ __align__(16) bf16  g_w3l [(size_t)XPROJ * D_INNER];
__device__ __align__(16) bf16  g_w4h [(size_t)D_INNER * DT_RANK];
__device__ __align__(16) bf16  g_w4l [(size_t)D_INNER * DT_RANK];
__device__ __align__(16) bf16  g_w6h [(size_t)D_MODEL * D_INNER];
__device__ __align__(16) bf16  g_w6l [(size_t)D_MODEL * D_INNER];

// ---------------- tiny PTX helpers -----------------------------------------
__device__ __forceinline__ uint32_t smem_u32(const void* p) {
    uint32_t a;
    asm("{ .reg .u64 t; cvta.to.shared.u64 t, %1; cvt.u32.u64 %0, t; }"
        : "=r"(a) : "l"(p));
    return a;
}
__device__ __forceinline__ uint32_t sw128(uint32_t off) {
    return off ^ ((off >> 3) & 0x70);
}
__device__ __forceinline__ void cpa16(uint32_t dst, const void* src, bool valid) {
    int sz = valid ? 16 : 0;
    asm volatile("cp.async.cg.shared.global [%0], [%1], 16, %2;"
                 :: "r"(dst), "l"(src), "r"(sz));
}
__device__ __forceinline__ void ldsm4(uint32_t* r, uint32_t addr) {
    asm volatile("ldmatrix.sync.aligned.m8n8.x4.shared.b16 {%0,%1,%2,%3}, [%4];"
                 : "=r"(r[0]), "=r"(r[1]), "=r"(r[2]), "=r"(r[3]) : "r"(addr));
}
__device__ __forceinline__ void mma_bf16(float* d, const uint32_t* a,
                                         uint32_t b0, uint32_t b1) {
    asm volatile(
        "mma.sync.aligned.m16n8k16.row.col.f32.bf16.bf16.f32 "
        "{%0,%1,%2,%3}, {%4,%5,%6,%7}, {%8,%9}, {%0,%1,%2,%3};"
        : "+f"(d[0]), "+f"(d[1]), "+f"(d[2]), "+f"(d[3])
        : "r"(a[0]), "r"(a[1]), "r"(a[2]), "r"(a[3]), "r"(b0), "r"(b1));
}

// ---------------- bf16 hi/lo split conversion ------------------------------
__global__ void split_kernel(const float* __restrict__ x,
                             bf16* __restrict__ h, bf16* __restrict__ l, int n)
{
    int i = blockIdx.x * blockDim.x + threadIdx.x;
    if (i < n) {
        float v = x[i];
        bf16 hb = __float2bfloat16(v);
        h[i] = hb;
        l[i] = __float2bfloat16(v - __bfloat162float(hb));
    }
}

// ---------------- HMMA bf16-split GEMM -------------------------------------
// C[M,N] = A[M,K] * B[N,K]^T, A/B pre-split into bf16 hi/lo, fp32 C.
// 128(M) x 128(N) CTA tile; 8 warps as 4(M) x 2(N); warp tile 32x64.
// K chunked by 64, 2-stage cp.async pipeline, SW128 smem, ldmatrix frags.
// 3-term split: Ah*Bh + Ah*Bl + Al*Bh (fp32 accumulate in registers).
// gridDim.z = split-K count; each z writes its own C slab (size M*ldc).
// EPI: 0 = plain store, 1 = add bias[col] then softplus.
#define KC 64
#define TILE_B   (128 * 128)            // 16 KB per bf16 tile (128 rows x 128B)
#define STAGE_B  (4 * TILE_B)           // Ah, Al, Bh, Bl = 64 KB
#define GEMM_SMEM (2 * STAGE_B + 1024)

template <int EPI>
__global__ __launch_bounds__(256, 1)
void gemm_bf16split(const bf16* __restrict__ Ah, const bf16* __restrict__ Al, int lda,
                    const bf16* __restrict__ Bh, const bf16* __restrict__ Bl, int ldb,
                    float* __restrict__ C, int ldc,
                    int M, int N, int Kslice,
                    const float* __restrict__ bias)
{
    extern __shared__ __align__(16) char dyns[];

    const int tid  = threadIdx.x;
    const int wid  = tid >> 5;
    const int lane = tid & 31;
    const int row0 = blockIdx.y * 128;
    const int col0 = blockIdx.x * 128;
    const int kBeg = blockIdx.z * Kslice;
    float* Cz = C + (size_t)blockIdx.z * (size_t)M * (size_t)ldc;
    const int nB = min(128, N - col0);
    const int chunks = Kslice / KC;

    const int warp_m = wid & 3;          // 0..3 -> 32 rows each
    const int warp_n = wid >> 2;         // 0..1 -> 64 cols each

    uint32_t sbase = (smem_u32(dyns) + 1023u) & ~1023u;

    float acc[2][8][4];
#pragma unroll
    for (int i = 0; i < 2; i++)
#pragma unroll
        for (int j = 0; j < 8; j++)
#pragma unroll
            for (int k = 0; k < 4; k++) acc[i][j][k] = 0.f;

    // chunk loader: 128 rows x 64 bf16 (=128B rows, SW128) for 4 tiles
    auto load_chunk = [&](int c) {
        uint32_t st = sbase + (uint32_t)(c & 1) * STAGE_B;
        int kcol = kBeg + c * KC;
        int seg = tid & 7;
#pragma unroll
        for (int j = 0; j < 4; j++) {
            int row = (tid >> 3) + j * 32;
            uint32_t so = sw128((uint32_t)(row * 128 + seg * 16));
            const bf16* pa  = Ah + (size_t)(row0 + row) * lda + kcol + seg * 8;
            const bf16* pal = Al + (size_t)(row0 + row) * lda + kcol + seg * 8;
            cpa16(st + so,          pa,  true);
            cpa16(st + TILE_B + so, pal, true);
            bool bv = row < nB;
            int  br = bv ? row : 0;
            const bf16* pb  = Bh + (size_t)(col0 + br) * ldb + kcol + seg * 8;
            const bf16* pbl = Bl + (size_t)(col0 + br) * ldb + kcol + seg * 8;
            cpa16(st + 2 * TILE_B + so, pb,  bv);
            cpa16(st + 3 * TILE_B + so, pbl, bv);
        }
        asm volatile("cp.async.commit_group;" ::: "memory");
    };

    load_chunk(0);

    // per-lane ldmatrix row/col-half
    const int lrow  = lane & 15;         // matrix row within 16
    const int lhalf = lane >> 4;         // 0: k-bytes 0..15, 1: 16..31

    for (int c = 0; c < chunks; c++) {
        if (c + 1 < chunks) {
            load_chunk(c + 1);
            asm volatile("cp.async.wait_group 1;" ::: "memory");
        } else {
            asm volatile("cp.async.wait_group 0;" ::: "memory");
        }
        __syncthreads();

        uint32_t st = sbase + (uint32_t)(c & 1) * STAGE_B;

#pragma unroll
        for (int ks = 0; ks < KC / 16; ks++) {
            const uint32_t kb = (uint32_t)(ks * 32 + lhalf * 16);

            uint32_t ah[2][4], al[2][4];
#pragma unroll
            for (int mf = 0; mf < 2; mf++) {
                int arow = warp_m * 32 + mf * 16 + lrow;
                uint32_t so = sw128((uint32_t)(arow * 128) + kb);
                ldsm4(ah[mf], st + so);
                ldsm4(al[mf], st + TILE_B + so);
            }
            uint32_t bh[4][4], bl[4][4];
#pragma unroll
            for (int nf = 0; nf < 4; nf++) {
                int brow = warp_n * 64 + nf * 16 + lrow;
                uint32_t so = sw128((uint32_t)(brow * 128) + kb);
                ldsm4(bh[nf], st + 2 * TILE_B + so);
                ldsm4(bl[nf], st + 3 * TILE_B + so);
            }
#pragma unroll
            for (int mf = 0; mf < 2; mf++) {
#pragma unroll
                for (int nf = 0; nf < 4; nf++) {
                    // hi*hi
                    mma_bf16(acc[mf][2 * nf],     ah[mf], bh[nf][0], bh[nf][2]);
                    mma_bf16(acc[mf][2 * nf + 1], ah[mf], bh[nf][1], bh[nf][3]);
                    // hi*lo
                    mma_bf16(acc[mf][2 * nf],     ah[mf], bl[nf][0], bl[nf][2]);
                    mma_bf16(acc[mf][2 * nf + 1], ah[mf], bl[nf][1], bl[nf][3]);
                    // lo*hi
                    mma_bf16(acc[mf][2 * nf],     al[mf], bh[nf][0], bh[nf][2]);
                    mma_bf16(acc[mf][2 * nf + 1], al[mf], bh[nf][1], bh[nf][3]);
                }
            }
        }
        __syncthreads();
    }

    // epilogue: register accumulators -> gmem
#pragma unroll
    for (int mf = 0; mf < 2; mf++) {
        int r = row0 + warp_m * 32 + mf * 16 + (lane >> 2);
#pragma unroll
        for (int j = 0; j < 8; j++) {
            int ccol = col0 + warp_n * 64 + j * 8 + (lane & 3) * 2;
            if (ccol < N) {
                float v0 = acc[mf][j][0], v1 = acc[mf][j][1];
                float v2 = acc[mf][j][2], v3 = acc[mf][j][3];
                if (EPI == 1) {
                    v0 += bias[ccol];     v1 += bias[ccol + 1];
                    v2 += bias[ccol];     v3 += bias[ccol + 1];
                    v0 = (v0 > 20.f) ? v0 : log1pf(expf(v0));
                    v1 = (v1 > 20.f) ? v1 : log1pf(expf(v1));
                    v2 = (v2 > 20.f) ? v2 : log1pf(expf(v2));
                    v3 = (v3 > 20.f) ? v3 : log1pf(expf(v3));
                }
                *(float2*)&Cz[(size_t)r * ldc + ccol]       = make_float2(v0, v1);
                *(float2*)&Cz[(size_t)(r + 8) * ldc + ccol] = make_float2(v2, v3);
            }
        }
    }
}

// ---------------- reduce split-K partials + dt_lr bf16 split ---------------
__global__ void reduce_part_kernel()
{
    int i = blockIdx.x * blockDim.x + threadIdx.x;
    if (i < BL * XPROJ) {
        float s = 0.f;
#pragma unroll
        for (int p = 0; p < KSPLIT; p++)
            s += g_part[(size_t)p * BL * XPROJ + i];
        g_xdbl[i] = s;
        int col = i % XPROJ;
        if (col < DT_RANK) {
            int row = i / XPROJ;
            bf16 hb = __float2bfloat16(s);
            g_dth[(size_t)row * DT_RANK + col] = hb;
            g_dtl[(size_t)row * DT_RANK + col] =
                __float2bfloat16(s - __bfloat162float(hb));
        }
    }
}

// ---------------- depthwise causal conv + bias + SiLU (+ bf16 split) -------
__global__ void conv_silu_kernel(const float* __restrict__ w,
                                 const float* __restrict__ bias)
{
    int idx = blockIdx.x * blockDim.x + threadIdx.x;
    if (idx >= BL * D_INNER) return;
    int d  = idx % D_INNER;
    int bl = idx / D_INNER;
    int l  = bl % SEQLEN;

    float acc = bias[d];
#pragma unroll
    for (int k = 0; k < D_CONV; k++) {
        int lk = l - (D_CONV - 1) + k;
        if (lk >= 0)
            acc += w[d * D_CONV + k] *
                   g_xz[(size_t)(bl - (D_CONV - 1 - k)) * (2 * D_INNER) + d];
    }
    float sg = 1.f / (1.f + expf(-acc));
    float v = acc * sg;
    g_xc[idx] = v;
    bf16 hb = __float2bfloat16(v);
    g_xch[idx] = hb;
    g_xcl[idx] = __float2bfloat16(v - __bfloat162float(hb));
}

// ---------------- selective scan + gating (writes y as bf16 hi/lo) ---------
__global__ __launch_bounds__(256)
void scan_kernel(const float* __restrict__ A_log,
                 const float* __restrict__ D_skip)
{
    const int TL = 64;
    __shared__ float sDelta[TL][16];
    __shared__ float sU[TL][16];
    __shared__ float sB[TL][16];
    __shared__ float sC[TL][16];
    __shared__ float sY[TL][16];

    const int b   = blockIdx.y;
    const int d0  = blockIdx.x * 16;
    const int tid = threadIdx.x;
    const int dc  = tid >> 4;
    const int n   = tid & 15;
    const int d   = d0 + dc;

    const float An = -expf(A_log[d * D_STATE + n]);
    float s = 0.f;

    for (int l0 = 0; l0 < SEQLEN; l0 += TL) {
        for (int i = tid; i < TL * 16; i += 256) {
            int t = i >> 4, c = i & 15;
            size_t row = (size_t)(b * SEQLEN + l0 + t);
            sDelta[t][c] = g_delta[row * D_INNER + d0 + c];
            sU[t][c]     = g_xc[row * D_INNER + d0 + c];
            sB[t][c]     = g_xdbl[row * XPROJ + DT_RANK + c];
            sC[t][c]     = g_xdbl[row * XPROJ + DT_RANK + D_STATE + c];
        }
        __syncthreads();

        for (int t = 0; t < TL; t++) {
            float dl = sDelta[t][dc];
            float dA = __expf(dl * An);
            s = fmaf(s, dA, (dl * sU[t][dc]) * sB[t][n]);
            float v = s * sC[t][n];
            v += __shfl_xor_sync(0xffffffffu, v, 8);
            v += __shfl_xor_sync(0xffffffffu, v, 4);
            v += __shfl_xor_sync(0xffffffffu, v, 2);
            v += __shfl_xor_sync(0xffffffffu, v, 1);
            if (n == 0) sY[t][dc] = v;
        }
        __syncthreads();

        for (int i = tid; i < TL * 16; i += 256) {
            int t = i >> 4, c = i & 15;
            size_t row = (size_t)(b * SEQLEN + l0 + t);
            float u  = sU[t][c];
            float yv = sY[t][c] + u * D_skip[d0 + c];
            float z  = g_xz[row * (2 * D_INNER) + D_INNER + d0 + c];
            yv *= z / (1.f + expf(-z));
            bf16 hb = __float2bfloat16(yv);
            g_yh[row * D_INNER + d0 + c] = hb;
            g_yl[row * D_INNER + d0 + c] =
                __float2bfloat16(yv - __bfloat162float(hb));
        }
        __syncthreads();
    }
}

// ---------------- launcher --------------------------------------------------
extern "C" void kernel_launch(void* const* d_in, const int* in_sizes, int n_in,
                              void* d_out, int out_size)
{
    const float* hidden     = (const float*)d_in[0];
    const float* in_proj_w  = (const float*)d_in[1];
    const float* conv_w     = (const float*)d_in[2];
    const float* conv_b     = (const float*)d_in[3];
    const float* x_proj_w   = (const float*)d_in[4];
    const float* dt_proj_w  = (const float*)d_in[5];
    const float* dt_proj_b  = (const float*)d_in[6];
    const float* A_log      = (const float*)d_in[7];
    const float* D_skip     = (const float*)d_in[8];
    const float* out_proj_w = (const float*)d_in[9];
    float* out = (float*)d_out;

    cudaFuncSetAttribute(gemm_bf16split<0>,
                         cudaFuncAttributeMaxDynamicSharedMemorySize, GEMM_SMEM);
    cudaFuncSetAttribute(gemm_bf16split<1>,
                         cudaFuncAttributeMaxDynamicSharedMemorySize, GEMM_SMEM);

    float *xz, *xdbl, *part, *delta;
    bf16 *xch, *xcl, *dth, *dtl, *yh, *yl, *hh, *hl;
    bf16 *w1h, *w1l, *w3h, *w3l, *w4h, *w4l, *w6h, *w6l;
    cudaGetSymbolAddress((void**)&xz,    g_xz);
    cudaGetSymbolAddress((void**)&xdbl,  g_xdbl);
    cudaGetSymbolAddress((void**)&part,  g_part);
    cudaGetSymbolAddress((void**)&delta, g_delta);
    cudaGetSymbolAddress((void**)&xch,   g_xch);
    cudaGetSymbolAddress((void**)&xcl,   g_xcl);
    cudaGetSymbolAddress((void**)&dth,   g_dth);
    cudaGetSymbolAddress((void**)&dtl,   g_dtl);
    cudaGetSymbolAddress((void**)&yh,    g_yh);
    cudaGetSymbolAddress((void**)&yl,    g_yl);
    cudaGetSymbolAddress((void**)&hh,    g_hh);
    cudaGetSymbolAddress((void**)&hl,    g_hl);
    cudaGetSymbolAddress((void**)&w1h,   g_w1h);
    cudaGetSymbolAddress((void**)&w1l,   g_w1l);
    cudaGetSymbolAddress((void**)&w3h,   g_w3h);
    cudaGetSymbolAddress((void**)&w3l,   g_w3l);
    cudaGetSymbolAddress((void**)&w4h,   g_w4h);
    cudaGetSymbolAddress((void**)&w4l,   g_w4l);
    cudaGetSymbolAddress((void**)&w6h,   g_w6h);
    cudaGetSymbolAddress((void**)&w6l,   g_w6l);

    // 0) bf16 hi/lo conversions
    split_kernel<<<(BL * D_MODEL + 255) / 256, 256>>>(hidden, hh, hl, BL * D_MODEL);
    split_kernel<<<(2 * D_INNER * D_MODEL + 255) / 256, 256>>>(in_proj_w, w1h, w1l,
                                                               2 * D_INNER * D_MODEL);
    split_kernel<<<(XPROJ * D_INNER + 255) / 256, 256>>>(x_proj_w, w3h, w3l,
                                                         XPROJ * D_INNER);
    split_kernel<<<(D_INNER * DT_RANK + 255) / 256, 256>>>(dt_proj_w, w4h, w4l,
                                                           D_INNER * DT_RANK);
    split_kernel<<<(D_MODEL * D_INNER + 255) / 256, 256>>>(out_proj_w, w6h, w6l,
                                                           D_MODEL * D_INNER);

    // 1) xz = hidden @ in_proj_w^T   (2048 x 4096 x 1024)
    gemm_bf16split<0><<<dim3(4096 / 128, BL / 128, 1), 256, GEMM_SMEM>>>(
        hh, hl, D_MODEL, w1h, w1l, D_MODEL, xz, 2 * D_INNER,
        BL, 2 * D_INNER, D_MODEL, nullptr);

    // 2) depthwise conv + SiLU -> xc (+ bf16 split)
    conv_silu_kernel<<<(BL * D_INNER + 255) / 256, 256>>>(conv_w, conv_b);

    // 3) x_dbl = xc @ x_proj_w^T    (2048 x 96 x 2048), split-K=8 + reduce
    gemm_bf16split<0><<<dim3(1, BL / 128, KSPLIT), 256, GEMM_SMEM>>>(
        xch, xcl, D_INNER, w3h, w3l, D_INNER, part, XPROJ,
        BL, XPROJ, D_INNER / KSPLIT, nullptr);
    reduce_part_kernel<<<(BL * XPROJ + 255) / 256, 256>>>();

    // 4) delta = softplus(dt_lr @ dt_proj_w^T + dt_b)  (2048 x 2048 x 64)
    gemm_bf16split<1><<<dim3(D_INNER / 128, BL / 128, 1), 256, GEMM_SMEM>>>(
        dth, dtl, DT_RANK, w4h, w4l, DT_RANK, delta, D_INNER,
        BL, D_INNER, DT_RANK, dt_proj_b);

    // 5) selective scan + gating -> y (bf16 hi/lo)
    scan_kernel<<<dim3(D_INNER / 16, BATCH), 256>>>(A_log, D_skip);

    // 6) out = y @ out_proj_w^T     (2048 x 1024 x 2048)
    gemm_bf16split<0><<<dim3(D_MODEL / 128, BL / 128, 1), 256, GEMM_SMEM>>>(
        yh, yl, D_INNER, w6h, w6l, D_INNER, out, D_MODEL,
        BL, D_MODEL, D_INNER, nullptr);
}

// round 4
// speedup vs baseline: 3.4415x; 1.4968x over previous
#include <cuda_runtime.h>
#include <cuda_fp16.h>
#include <math.h>
#include <stdint.h>

#define D_MODEL 1024
#define D_INNER 2048
#define D_STATE 16
#define D_CONV  4
#define DT_RANK 64
#define BATCH   2
#define SEQLEN  1024
#define BL      (BATCH * SEQLEN)          // 2048 rows
#define XPROJ   (DT_RANK + 2 * D_STATE)   // 96
#define KSPLIT  8

// ---------------- scratch (static device globals; no allocs allowed) -------
__device__ __align__(16) float  g_xz  [(size_t)BL * 2 * D_INNER];   // 32 MB
__device__ __align__(16) float  g_xc  [(size_t)BL * D_INNER];       // 16 MB
__device__ __align__(16) __half g_xch [(size_t)BL * D_INNER];
__device__ __align__(16) float  g_xdbl[(size_t)BL * XPROJ];
__device__ __align__(16) float  g_part[(size_t)KSPLIT * BL * XPROJ];
__device__ __align__(16) __half g_dth [(size_t)BL * DT_RANK];
__device__ __align__(16) float  g_delta[(size_t)BL * D_INNER];      // 16 MB
__device__ __align__(16) __half g_yh  [(size_t)BL * D_INNER];
__device__ __align__(16) __half g_hh  [(size_t)BL * D_MODEL];
__device__ __align__(16) __half g_w1h [(size_t)2 * D_INNER * D_MODEL];
__device__ __align__(16) __half g_w3h [(size_t)XPROJ * D_INNER];
__device__ __align__(16) __half g_w4h [(size_t)D_INNER * DT_RANK];
__device__ __align__(16) __half g_w6h [(size_t)D_MODEL * D_INNER];

// ---------------- tiny PTX helpers -----------------------------------------
__device__ __forceinline__ uint32_t smem_u32(const void* p) {
    uint32_t a;
    asm("{ .reg .u64 t; cvta.to.shared.u64 t, %1; cvt.u32.u64 %0, t; }"
        : "=r"(a) : "l"(p));
    return a;
}
__device__ __forceinline__ uint32_t sw128(uint32_t off) {
    return off ^ ((off >> 3) & 0x70);
}
__device__ __forceinline__ void cpa16(uint32_t dst, const void* src, bool valid) {
    int sz = valid ? 16 : 0;
    asm volatile("cp.async.cg.shared.global [%0], [%1], 16, %2;"
                 :: "r"(dst), "l"(src), "r"(sz));
}
__device__ __forceinline__ void ldsm4(uint32_t* r, uint32_t addr) {
    asm volatile("ldmatrix.sync.aligned.m8n8.x4.shared.b16 {%0,%1,%2,%3}, [%4];"
                 : "=r"(r[0]), "=r"(r[1]), "=r"(r[2]), "=r"(r[3]) : "r"(addr));
}
__device__ __forceinline__ void mma_f16(float* d, const uint32_t* a,
                                        uint32_t b0, uint32_t b1) {
    asm volatile(
        "mma.sync.aligned.m16n8k16.row.col.f32.f16.f16.f32 "
        "{%0,%1,%2,%3}, {%4,%5,%6,%7}, {%8,%9}, {%0,%1,%2,%3};"
        : "+f"(d[0]), "+f"(d[1]), "+f"(d[2]), "+f"(d[3])
        : "r"(a[0]), "r"(a[1]), "r"(a[2]), "r"(a[3]), "r"(b0), "r"(b1));
}

// ---------------- fp32 -> fp16 conversion (vectorized) ----------------------
__global__ void cvt_kernel(const float* __restrict__ x,
                           __half* __restrict__ h, int n4)
{
    int i = blockIdx.x * blockDim.x + threadIdx.x;
    if (i < n4) {
        float4 v = ((const float4*)x)[i];
        __half2 a = __floats2half2_rn(v.x, v.y);
        __half2 b = __floats2half2_rn(v.z, v.w);
        ((uint2*)h)[i] = make_uint2(*(uint32_t*)&a, *(uint32_t*)&b);
    }
}

// ---------------- HMMA fp16 GEMM -------------------------------------------
// C[M,N] = A[M,K] * B[N,K]^T, fp16 inputs, fp32 accum/out.
// 128(M) x 128(N) CTA tile; 8 warps as 4(M) x 2(N); warp tile 32x64.
// K chunked by 64; 4-stage cp.async pipeline; SW128 smem; ldmatrix frags.
// gridDim.z = split-K count; each z writes its own C slab (size M*ldc).
// EPI: 0 = plain store, 1 = add bias[col] then softplus.
#define KC 64
#define TILE_B   (128 * 128)            // 16 KB per fp16 tile (128 rows x 128B)
#define STAGE_B  (2 * TILE_B)           // A, B = 32 KB
#define NSTAGE   4
#define GEMM_SMEM (NSTAGE * STAGE_B + 1024)

template <int EPI>
__global__ __launch_bounds__(256, 1)
void gemm_f16(const __half* __restrict__ A, int lda,
              const __half* __restrict__ B, int ldb,
              float* __restrict__ C, int ldc,
              int M, int N, int Kslice,
              const float* __restrict__ bias)
{
    extern __shared__ __align__(16) char dyns[];

    const int tid  = threadIdx.x;
    const int wid  = tid >> 5;
    const int lane = tid & 31;
    const int row0 = blockIdx.y * 128;
    const int col0 = blockIdx.x * 128;
    const int kBeg = blockIdx.z * Kslice;
    float* Cz = C + (size_t)blockIdx.z * (size_t)M * (size_t)ldc;
    const int nB = min(128, N - col0);
    const int chunks = Kslice / KC;

    const int warp_m = wid & 3;          // 0..3 -> 32 rows each
    const int warp_n = wid >> 2;         // 0..1 -> 64 cols each

    uint32_t sbase = (smem_u32(dyns) + 1023u) & ~1023u;

    float acc[2][8][4];
#pragma unroll
    for (int i = 0; i < 2; i++)
#pragma unroll
        for (int j = 0; j < 8; j++)
#pragma unroll
            for (int k = 0; k < 4; k++) acc[i][j][k] = 0.f;

    // chunk loader: 128 rows x 64 fp16 (=128B rows, SW128) for A and B tiles
    auto load_chunk = [&](int c) {
        uint32_t st = sbase + (uint32_t)(c & (NSTAGE - 1)) * STAGE_B;
        int kcol = kBeg + c * KC;
        int seg = tid & 7;
#pragma unroll
        for (int j = 0; j < 4; j++) {
            int row = (tid >> 3) + j * 32;
            uint32_t so = sw128((uint32_t)(row * 128 + seg * 16));
            const __half* pa = A + (size_t)(row0 + row) * lda + kcol + seg * 8;
            cpa16(st + so, pa, true);
            bool bv = row < nB;
            int  br = bv ? row : 0;
            const __half* pb = B + (size_t)(col0 + br) * ldb + kcol + seg * 8;
            cpa16(st + TILE_B + so, pb, bv);
        }
        asm volatile("cp.async.commit_group;" ::: "memory");
    };

    // preload up to NSTAGE-1 chunks
#pragma unroll
    for (int p = 0; p < NSTAGE - 1; p++)
        if (p < chunks) load_chunk(p);

    const int lrow  = lane & 15;
    const int lhalf = lane >> 4;

    for (int c = 0; c < chunks; c++) {
        int pend = chunks - 1 - c;                  // groups issued after c
        if (pend > NSTAGE - 2) pend = NSTAGE - 2;   // cap by pipeline depth
        if (pend == 2)      asm volatile("cp.async.wait_group 2;" ::: "memory");
        else if (pend == 1) asm volatile("cp.async.wait_group 1;" ::: "memory");
        else                asm volatile("cp.async.wait_group 0;" ::: "memory");
        __syncthreads();

        if (c + NSTAGE - 1 < chunks) load_chunk(c + NSTAGE - 1);

        uint32_t st = sbase + (uint32_t)(c & (NSTAGE - 1)) * STAGE_B;

#pragma unroll
        for (int ks = 0; ks < KC / 16; ks++) {
            const uint32_t kb = (uint32_t)(ks * 32 + lhalf * 16);

            uint32_t af[2][4];
#pragma unroll
            for (int mf = 0; mf < 2; mf++) {
                int arow = warp_m * 32 + mf * 16 + lrow;
                ldsm4(af[mf], st + sw128((uint32_t)(arow * 128) + kb));
            }
            uint32_t bf[4][4];
#pragma unroll
            for (int nf = 0; nf < 4; nf++) {
                int brow = warp_n * 64 + nf * 16 + lrow;
                ldsm4(bf[nf], st + TILE_B + sw128((uint32_t)(brow * 128) + kb));
            }
#pragma unroll
            for (int mf = 0; mf < 2; mf++) {
#pragma unroll
                for (int nf = 0; nf < 4; nf++) {
                    mma_f16(acc[mf][2 * nf],     af[mf], bf[nf][0], bf[nf][2]);
                    mma_f16(acc[mf][2 * nf + 1], af[mf], bf[nf][1], bf[nf][3]);
                }
            }
        }
        __syncthreads();
    }

    // epilogue: register accumulators -> gmem
#pragma unroll
    for (int mf = 0; mf < 2; mf++) {
        int r = row0 + warp_m * 32 + mf * 16 + (lane >> 2);
#pragma unroll
        for (int j = 0; j < 8; j++) {
            int ccol = col0 + warp_n * 64 + j * 8 + (lane & 3) * 2;
            if (ccol < N) {
                float v0 = acc[mf][j][0], v1 = acc[mf][j][1];
                float v2 = acc[mf][j][2], v3 = acc[mf][j][3];
                if (EPI == 1) {
                    v0 += bias[ccol];     v1 += bias[ccol + 1];
                    v2 += bias[ccol];     v3 += bias[ccol + 1];
                    v0 = (v0 > 20.f) ? v0 : log1pf(expf(v0));
                    v1 = (v1 > 20.f) ? v1 : log1pf(expf(v1));
                    v2 = (v2 > 20.f) ? v2 : log1pf(expf(v2));
                    v3 = (v3 > 20.f) ? v3 : log1pf(expf(v3));
                }
                *(float2*)&Cz[(size_t)r * ldc + ccol]       = make_float2(v0, v1);
                *(float2*)&Cz[(size_t)(r + 8) * ldc + ccol] = make_float2(v2, v3);
            }
        }
    }
}

// ---------------- reduce split-K partials + dt_lr fp16 ----------------------
__global__ void reduce_part_kernel()
{
    int i = blockIdx.x * blockDim.x + threadIdx.x;
    if (i < BL * XPROJ) {
        float s = 0.f;
#pragma unroll
        for (int p = 0; p < KSPLIT; p++)
            s += g_part[(size_t)p * BL * XPROJ + i];
        g_xdbl[i] = s;
        int col = i % XPROJ;
        if (col < DT_RANK) {
            int row = i / XPROJ;
            g_dth[(size_t)row * DT_RANK + col] = __float2half_rn(s);
        }
    }
}

// ---------------- depthwise causal conv + bias + SiLU (+ fp16 copy) --------
__global__ void conv_silu_kernel(const float* __restrict__ w,
                                 const float* __restrict__ bias)
{
    int idx = blockIdx.x * blockDim.x + threadIdx.x;
    if (idx >= BL * D_INNER) return;
    int d  = idx % D_INNER;
    int bl = idx / D_INNER;
    int l  = bl % SEQLEN;

    float acc = bias[d];
#pragma unroll
    for (int k = 0; k < D_CONV; k++) {
        int lk = l - (D_CONV - 1) + k;
        if (lk >= 0)
            acc += w[d * D_CONV + k] *
                   g_xz[(size_t)(bl - (D_CONV - 1 - k)) * (2 * D_INNER) + d];
    }
    float sg = 1.f / (1.f + expf(-acc));
    float v = acc * sg;
    g_xc[idx]  = v;
    g_xch[idx] = __float2half_rn(v);
}

// ---------------- selective scan + gating (writes y as fp16) ----------------
__global__ __launch_bounds__(256)
void scan_kernel(const float* __restrict__ A_log,
                 const float* __restrict__ D_skip)
{
    const int TL = 64;
    __shared__ float sDelta[TL][16];
    __shared__ float sU[TL][16];
    __shared__ float sB[TL][16];
    __shared__ float sC[TL][16];
    __shared__ float sY[TL][16];

    const int b   = blockIdx.y;
    const int d0  = blockIdx.x * 16;
    const int tid = threadIdx.x;
    const int dc  = tid >> 4;
    const int n   = tid & 15;
    const int d   = d0 + dc;

    const float An = -expf(A_log[d * D_STATE + n]);
    float s = 0.f;

    for (int l0 = 0; l0 < SEQLEN; l0 += TL) {
        for (int i = tid; i < TL * 16; i += 256) {
            int t = i >> 4, c = i & 15;
            size_t row = (size_t)(b * SEQLEN + l0 + t);
            sDelta[t][c] = g_delta[row * D_INNER + d0 + c];
            sU[t][c]     = g_xc[row * D_INNER + d0 + c];
            sB[t][c]     = g_xdbl[row * XPROJ + DT_RANK + c];
            sC[t][c]     = g_xdbl[row * XPROJ + DT_RANK + D_STATE + c];
        }
        __syncthreads();

        for (int t = 0; t < TL; t++) {
            float dl = sDelta[t][dc];
            float dA = __expf(dl * An);
            s = fmaf(s, dA, (dl * sU[t][dc]) * sB[t][n]);
            float v = s * sC[t][n];
            v += __shfl_xor_sync(0xffffffffu, v, 8);
            v += __shfl_xor_sync(0xffffffffu, v, 4);
            v += __shfl_xor_sync(0xffffffffu, v, 2);
            v += __shfl_xor_sync(0xffffffffu, v, 1);
            if (n == 0) sY[t][dc] = v;
        }
        __syncthreads();

        for (int i = tid; i < TL * 16; i += 256) {
            int t = i >> 4, c = i & 15;
            size_t row = (size_t)(b * SEQLEN + l0 + t);
            float u  = sU[t][c];
            float yv = sY[t][c] + u * D_skip[d0 + c];
            float z  = g_xz[row * (2 * D_INNER) + D_INNER + d0 + c];
            yv *= z / (1.f + expf(-z));
            g_yh[row * D_INNER + d0 + c] = __float2half_rn(yv);
        }
        __syncthreads();
    }
}

// ---------------- launcher --------------------------------------------------
extern "C" void kernel_launch(void* const* d_in, const int* in_sizes, int n_in,
                              void* d_out, int out_size)
{
    const float* hidden     = (const float*)d_in[0];
    const float* in_proj_w  = (const float*)d_in[1];
    const float* conv_w     = (const float*)d_in[2];
    const float* conv_b     = (const float*)d_in[3];
    const float* x_proj_w   = (const float*)d_in[4];
    const float* dt_proj_w  = (const float*)d_in[5];
    const float* dt_proj_b  = (const float*)d_in[6];
    const float* A_log      = (const float*)d_in[7];
    const float* D_skip     = (const float*)d_in[8];
    const float* out_proj_w = (const float*)d_in[9];
    float* out = (float*)d_out;

    cudaFuncSetAttribute(gemm_f16<0>,
                         cudaFuncAttributeMaxDynamicSharedMemorySize, GEMM_SMEM);
    cudaFuncSetAttribute(gemm_f16<1>,
                         cudaFuncAttributeMaxDynamicSharedMemorySize, GEMM_SMEM);

    float *xz, *xdbl, *part, *delta;
    __half *xch, *dth, *yh, *hh, *w1h, *w3h, *w4h, *w6h;
    cudaGetSymbolAddress((void**)&xz,    g_xz);
    cudaGetSymbolAddress((void**)&xdbl,  g_xdbl);
    cudaGetSymbolAddress((void**)&part,  g_part);
    cudaGetSymbolAddress((void**)&delta, g_delta);
    cudaGetSymbolAddress((void**)&xch,   g_xch);
    cudaGetSymbolAddress((void**)&dth,   g_dth);
    cudaGetSymbolAddress((void**)&yh,    g_yh);
    cudaGetSymbolAddress((void**)&hh,    g_hh);
    cudaGetSymbolAddress((void**)&w1h,   g_w1h);
    cudaGetSymbolAddress((void**)&w3h,   g_w3h);
    cudaGetSymbolAddress((void**)&w4h,   g_w4h);
    cudaGetSymbolAddress((void**)&w6h,   g_w6h);

    // launch index 3 (as seen by ncu -s) = gemm1, for profiling visibility.
    // 0) conversions needed by gemm1
    cvt_kernel<<<(2 * D_INNER * D_MODEL / 4 + 255) / 256, 256>>>(
        in_proj_w, w1h, 2 * D_INNER * D_MODEL / 4);
    cvt_kernel<<<(D_MODEL * D_INNER / 4 + 255) / 256, 256>>>(
        out_proj_w, w6h, D_MODEL * D_INNER / 4);
    cvt_kernel<<<(BL * D_MODEL / 4 + 255) / 256, 256>>>(
        hidden, hh, BL * D_MODEL / 4);

    // 1) xz = hidden @ in_proj_w^T   (2048 x 4096 x 1024)
    gemm_f16<0><<<dim3(4096 / 128, BL / 128, 1), 256, GEMM_SMEM>>>(
        hh, D_MODEL, w1h, D_MODEL, xz, 2 * D_INNER,
        BL, 2 * D_INNER, D_MODEL, nullptr);

    // remaining conversions
    cvt_kernel<<<(XPROJ * D_INNER / 4 + 255) / 256, 256>>>(
        x_proj_w, w3h, XPROJ * D_INNER / 4);
    cvt_kernel<<<(D_INNER * DT_RANK / 4 + 255) / 256, 256>>>(
        dt_proj_w, w4h, D_INNER * DT_RANK / 4);

    // 2) depthwise conv + SiLU -> xc (+ fp16 copy)
    conv_silu_kernel<<<(BL * D_INNER + 255) / 256, 256>>>(conv_w, conv_b);

    // 3) x_dbl = xc @ x_proj_w^T    (2048 x 96 x 2048), split-K=8 + reduce
    gemm_f16<0><<<dim3(1, BL / 128, KSPLIT), 256, GEMM_SMEM>>>(
        xch, D_INNER, w3h, D_INNER, part, XPROJ,
        BL, XPROJ, D_INNER / KSPLIT, nullptr);
    reduce_part_kernel<<<(BL * XPROJ + 255) / 256, 256>>>();

    // 4) delta = softplus(dt_lr @ dt_proj_w^T + dt_b)  (2048 x 2048 x 64)
    gemm_f16<1><<<dim3(D_INNER / 128, BL / 128, 1), 256, GEMM_SMEM>>>(
        dth, DT_RANK, w4h, DT_RANK, delta, D_INNER,
        BL, D_INNER, DT_RANK, dt_proj_b);

    // 5) selective scan + gating -> y (fp16)
    scan_kernel<<<dim3(D_INNER / 16, BATCH), 256>>>(A_log, D_skip);

    // 6) out = y @ out_proj_w^T     (2048 x 1024 x 2048)
    gemm_f16<0><<<dim3(D_MODEL / 128, BL / 128, 1), 256, GEMM_SMEM>>>(
        yh, D_INNER, w6h, D_INNER, out, D_MODEL,
        BL, D_MODEL, D_INNER, nullptr);
}

// round 5
// speedup vs baseline: 3.8006x; 1.1044x over previous
#include <cuda_runtime.h>
#include <cuda_fp16.h>
#include <math.h>
#include <stdint.h>

#define D_MODEL 1024
#define D_INNER 2048
#define D_STATE 16
#define D_CONV  4
#define DT_RANK 64
#define BATCH   2
#define SEQLEN  1024
#define BL      (BATCH * SEQLEN)          // 2048 rows
#define XPROJ   (DT_RANK + 2 * D_STATE)   // 96
#define KSPLIT  8

// ---------------- scratch (static device globals; no allocs allowed) -------
__device__ __align__(16) float  g_xz  [(size_t)BL * 2 * D_INNER];   // 32 MB
__device__ __align__(16) float  g_xc  [(size_t)BL * D_INNER];       // 16 MB
__device__ __align__(16) __half g_xch [(size_t)BL * D_INNER];
__device__ __align__(16) float  g_xdbl[(size_t)BL * XPROJ];
__device__ __align__(16) float  g_part[(size_t)KSPLIT * BL * XPROJ];
__device__ __align__(16) __half g_dth [(size_t)BL * DT_RANK];
__device__ __align__(16) float  g_delta[(size_t)BL * D_INNER];      // 16 MB
__device__ __align__(16) __half g_yh  [(size_t)BL * D_INNER];
__device__ __align__(16) __half g_hh  [(size_t)BL * D_MODEL];
__device__ __align__(16) __half g_w1h [(size_t)2 * D_INNER * D_MODEL];
__device__ __align__(16) __half g_w3h [(size_t)XPROJ * D_INNER];
__device__ __align__(16) __half g_w4h [(size_t)D_INNER * DT_RANK];
__device__ __align__(16) __half g_w6h [(size_t)D_MODEL * D_INNER];

// ---------------- tiny PTX helpers -----------------------------------------
__device__ __forceinline__ uint32_t smem_u32(const void* p) {
    uint32_t a;
    asm("{ .reg .u64 t; cvta.to.shared.u64 t, %1; cvt.u32.u64 %0, t; }"
        : "=r"(a) : "l"(p));
    return a;
}
__device__ __forceinline__ uint32_t sw128(uint32_t off) {
    return off ^ ((off >> 3) & 0x70);
}
__device__ __forceinline__ void cpa16(uint32_t dst, const void* src, bool valid) {
    int sz = valid ? 16 : 0;
    asm volatile("cp.async.cg.shared.global [%0], [%1], 16, %2;"
                 :: "r"(dst), "l"(src), "r"(sz));
}
__device__ __forceinline__ void cpa16ca(uint32_t dst, const void* src) {
    asm volatile("cp.async.ca.shared.global [%0], [%1], 16;"
                 :: "r"(dst), "l"(src));
}
__device__ __forceinline__ void ldsm4(uint32_t* r, uint32_t addr) {
    asm volatile("ldmatrix.sync.aligned.m8n8.x4.shared.b16 {%0,%1,%2,%3}, [%4];"
                 : "=r"(r[0]), "=r"(r[1]), "=r"(r[2]), "=r"(r[3]) : "r"(addr));
}
__device__ __forceinline__ void mma_f16(float* d, const uint32_t* a,
                                        uint32_t b0, uint32_t b1) {
    asm volatile(
        "mma.sync.aligned.m16n8k16.row.col.f32.f16.f16.f32 "
        "{%0,%1,%2,%3}, {%4,%5,%6,%7}, {%8,%9}, {%0,%1,%2,%3};"
        : "+f"(d[0]), "+f"(d[1]), "+f"(d[2]), "+f"(d[3])
        : "r"(a[0]), "r"(a[1]), "r"(a[2]), "r"(a[3]), "r"(b0), "r"(b1));
}

// ---------------- fp32 -> fp16 conversion (vectorized) ----------------------
__global__ void cvt_kernel(const float* __restrict__ x,
                           __half* __restrict__ h, int n4)
{
    int i = blockIdx.x * blockDim.x + threadIdx.x;
    if (i < n4) {
        float4 v = ((const float4*)x)[i];
        __half2 a = __floats2half2_rn(v.x, v.y);
        __half2 b = __floats2half2_rn(v.z, v.w);
        ((uint2*)h)[i] = make_uint2(*(uint32_t*)&a, *(uint32_t*)&b);
    }
}

// ---------------- HMMA fp16 GEMM -------------------------------------------
// C[M,N] = A[M,K] * B[N,K]^T, fp16 inputs, fp32 accum/out.
// 128x128 CTA tile; 8 warps 4(M)x2(N); warp tile 32x64.
// KC=64; 3-stage cp.async pipeline; SW128 smem; 2 CTAs/SM.
#define KC 64
#define TILE_B   (128 * 128)            // 16 KB per fp16 tile
#define STAGE_B  (2 * TILE_B)           // A, B = 32 KB
#define NSTAGE   3
#define GEMM_SMEM (NSTAGE * STAGE_B + 1024)

template <int EPI>
__global__ __launch_bounds__(256, 2)
void gemm_f16(const __half* __restrict__ A, int lda,
              const __half* __restrict__ B, int ldb,
              float* __restrict__ C, int ldc,
              int M, int N, int Kslice,
              const float* __restrict__ bias)
{
    extern __shared__ __align__(16) char dyns[];

    const int tid  = threadIdx.x;
    const int wid  = tid >> 5;
    const int lane = tid & 31;
    const int row0 = blockIdx.y * 128;
    const int col0 = blockIdx.x * 128;
    const int kBeg = blockIdx.z * Kslice;
    float* Cz = C + (size_t)blockIdx.z * (size_t)M * (size_t)ldc;
    const int nB = min(128, N - col0);
    const int chunks = Kslice / KC;

    const int warp_m = wid & 3;
    const int warp_n = wid >> 2;

    uint32_t sbase = (smem_u32(dyns) + 1023u) & ~1023u;

    float acc[2][8][4];
#pragma unroll
    for (int i = 0; i < 2; i++)
#pragma unroll
        for (int j = 0; j < 8; j++)
#pragma unroll
            for (int k = 0; k < 4; k++) acc[i][j][k] = 0.f;

    auto load_chunk = [&](int c) {
        uint32_t st = sbase + (uint32_t)(c % NSTAGE) * STAGE_B;
        int kcol = kBeg + c * KC;
        int seg = tid & 7;
#pragma unroll
        for (int j = 0; j < 4; j++) {
            int row = (tid >> 3) + j * 32;
            uint32_t so = sw128((uint32_t)(row * 128 + seg * 16));
            const __half* pa = A + (size_t)(row0 + row) * lda + kcol + seg * 8;
            cpa16(st + so, pa, true);
            bool bv = row < nB;
            int  br = bv ? row : 0;
            const __half* pb = B + (size_t)(col0 + br) * ldb + kcol + seg * 8;
            cpa16(st + TILE_B + so, pb, bv);
        }
        asm volatile("cp.async.commit_group;" ::: "memory");
    };

#pragma unroll
    for (int p = 0; p < NSTAGE - 1; p++)
        if (p < chunks) load_chunk(p);

    const int lrow  = lane & 15;
    const int lhalf = lane >> 4;

    for (int c = 0; c < chunks; c++) {
        int pend = chunks - 1 - c;
        if (pend > NSTAGE - 2) pend = NSTAGE - 2;
        if (pend == 1) asm volatile("cp.async.wait_group 1;" ::: "memory");
        else           asm volatile("cp.async.wait_group 0;" ::: "memory");
        __syncthreads();

        if (c + NSTAGE - 1 < chunks) load_chunk(c + NSTAGE - 1);

        uint32_t st = sbase + (uint32_t)(c % NSTAGE) * STAGE_B;

#pragma unroll
        for (int ks = 0; ks < KC / 16; ks++) {
            const uint32_t kb = (uint32_t)(ks * 32 + lhalf * 16);

            uint32_t af[2][4];
#pragma unroll
            for (int mf = 0; mf < 2; mf++) {
                int arow = warp_m * 32 + mf * 16 + lrow;
                ldsm4(af[mf], st + sw128((uint32_t)(arow * 128) + kb));
            }
            uint32_t bf[4][4];
#pragma unroll
            for (int nf = 0; nf < 4; nf++) {
                int brow = warp_n * 64 + nf * 16 + lrow;
                ldsm4(bf[nf], st + TILE_B + sw128((uint32_t)(brow * 128) + kb));
            }
#pragma unroll
            for (int mf = 0; mf < 2; mf++) {
#pragma unroll
                for (int nf = 0; nf < 4; nf++) {
                    mma_f16(acc[mf][2 * nf],     af[mf], bf[nf][0], bf[nf][2]);
                    mma_f16(acc[mf][2 * nf + 1], af[mf], bf[nf][1], bf[nf][3]);
                }
            }
        }
        __syncthreads();
    }

#pragma unroll
    for (int mf = 0; mf < 2; mf++) {
        int r = row0 + warp_m * 32 + mf * 16 + (lane >> 2);
#pragma unroll
        for (int j = 0; j < 8; j++) {
            int ccol = col0 + warp_n * 64 + j * 8 + (lane & 3) * 2;
            if (ccol < N) {
                float v0 = acc[mf][j][0], v1 = acc[mf][j][1];
                float v2 = acc[mf][j][2], v3 = acc[mf][j][3];
                if (EPI == 1) {
                    v0 += bias[ccol];     v1 += bias[ccol + 1];
                    v2 += bias[ccol];     v3 += bias[ccol + 1];
                    v0 = (v0 > 20.f) ? v0 : log1pf(expf(v0));
                    v1 = (v1 > 20.f) ? v1 : log1pf(expf(v1));
                    v2 = (v2 > 20.f) ? v2 : log1pf(expf(v2));
                    v3 = (v3 > 20.f) ? v3 : log1pf(expf(v3));
                }
                *(float2*)&Cz[(size_t)r * ldc + ccol]       = make_float2(v0, v1);
                *(float2*)&Cz[(size_t)(r + 8) * ldc + ccol] = make_float2(v2, v3);
            }
        }
    }
}

// ---------------- reduce split-K partials + dt_lr fp16 ----------------------
__global__ void reduce_part_kernel()
{
    int i = blockIdx.x * blockDim.x + threadIdx.x;
    if (i < BL * XPROJ) {
        float s = 0.f;
#pragma unroll
        for (int p = 0; p < KSPLIT; p++)
            s += g_part[(size_t)p * BL * XPROJ + i];
        g_xdbl[i] = s;
        int col = i % XPROJ;
        if (col < DT_RANK) {
            int row = i / XPROJ;
            g_dth[(size_t)row * DT_RANK + col] = __float2half_rn(s);
        }
    }
}

// ---------------- depthwise causal conv + bias + SiLU (+ fp16 copy) --------
__global__ void conv_silu_kernel(const float* __restrict__ w,
                                 const float* __restrict__ bias)
{
    int idx = blockIdx.x * blockDim.x + threadIdx.x;
    if (idx >= BL * D_INNER) return;
    int d  = idx % D_INNER;
    int bl = idx / D_INNER;
    int l  = bl % SEQLEN;

    float acc = bias[d];
#pragma unroll
    for (int k = 0; k < D_CONV; k++) {
        int lk = l - (D_CONV - 1) + k;
        if (lk >= 0)
            acc += w[d * D_CONV + k] *
                   g_xz[(size_t)(bl - (D_CONV - 1 - k)) * (2 * D_INNER) + d];
    }
    float sg = 1.f / (1.f + expf(-acc));
    float v = acc * sg;
    g_xc[idx]  = v;
    g_xch[idx] = __float2half_rn(v);
}

// ---------------- selective scan + gating (512 thr, 32 channels/block) -----
// grid (D_INNER/32, BATCH) = (64, 2) = 128 blocks ~= 1 per SM.
// Thread (dc, n): channel d0+dc, state n. cp.async double-buffered staging.
#define TL 64
__global__ __launch_bounds__(512)
void scan_kernel(const float* __restrict__ A_log,
                 const float* __restrict__ D_skip)
{
    __shared__ float sD[2][TL][32];
    __shared__ float sU[2][TL][32];
    __shared__ float sB[2][TL][16];
    __shared__ float sC[2][TL][16];
    __shared__ float sY[TL][32];

    const int b   = blockIdx.y;
    const int d0  = blockIdx.x * 32;
    const int tid = threadIdx.x;
    const int dc  = tid >> 4;   // 0..31
    const int n   = tid & 15;   // 0..15
    const int d   = d0 + dc;

    const float An = -expf(A_log[d * D_STATE + n]);
    const float Dskip = D_skip[d0 + (tid & 31)];
    float s = 0.f;

    // stage chunk c into buffer c&1
    auto stage = [&](int c) {
        int buf = c & 1;
        int l0 = c * TL;
        {   // delta & u: 64 t x 8 segs of 16B
            int t = tid >> 3, seg = tid & 7;
            size_t row = (size_t)(b * SEQLEN + l0 + t);
            cpa16ca(smem_u32(&sD[buf][t][seg * 4]),
                    &g_delta[row * D_INNER + d0 + seg * 4]);
            cpa16ca(smem_u32(&sU[buf][t][seg * 4]),
                    &g_xc[row * D_INNER + d0 + seg * 4]);
        }
        if (tid < 256) {  // B: 64 t x 4 segs
            int t = tid >> 2, seg = tid & 3;
            size_t row = (size_t)(b * SEQLEN + l0 + t);
            cpa16ca(smem_u32(&sB[buf][t][seg * 4]),
                    &g_xdbl[row * XPROJ + DT_RANK + seg * 4]);
        } else if (tid < 512) {  // C
            int t2 = tid - 256;
            int t = t2 >> 2, seg = t2 & 3;
            size_t row = (size_t)(b * SEQLEN + l0 + t);
            cpa16ca(smem_u32(&sC[buf][t][seg * 4]),
                    &g_xdbl[row * XPROJ + DT_RANK + D_STATE + seg * 4]);
        }
        asm volatile("cp.async.commit_group;" ::: "memory");
    };

    const int NCH = SEQLEN / TL;   // 16 chunks
    stage(0);

    for (int c = 0; c < NCH; c++) {
        if (c + 1 < NCH) {
            stage(c + 1);
            asm volatile("cp.async.wait_group 1;" ::: "memory");
        } else {
            asm volatile("cp.async.wait_group 0;" ::: "memory");
        }
        __syncthreads();

        const int buf = c & 1;
#pragma unroll 4
        for (int t = 0; t < TL; t++) {
            float dl = sD[buf][t][dc];
            float u  = sU[buf][t][dc];
            float dA = __expf(dl * An);
            s = fmaf(s, dA, (dl * u) * sB[buf][t][n]);
            float v = s * sC[buf][t][n];
            v += __shfl_xor_sync(0xffffffffu, v, 8);
            v += __shfl_xor_sync(0xffffffffu, v, 4);
            v += __shfl_xor_sync(0xffffffffu, v, 2);
            v += __shfl_xor_sync(0xffffffffu, v, 1);
            if (n == 0) sY[t][dc] = v;
        }
        __syncthreads();

        // epilogue: (y + u*D) * silu(z) -> fp16
        {
            int l0 = c * TL;
            for (int i = tid; i < TL * 32; i += 512) {
                int t = i >> 5, ch = i & 31;
                size_t row = (size_t)(b * SEQLEN + l0 + t);
                float u  = sU[buf][t][ch];
                float yv = sY[t][ch] + u * Dskip;
                float z  = g_xz[row * (2 * D_INNER) + D_INNER + d0 + ch];
                yv *= z / (1.f + expf(-z));
                g_yh[row * D_INNER + d0 + ch] = __float2half_rn(yv);
            }
        }
        __syncthreads();
    }
}

// ---------------- launcher --------------------------------------------------
extern "C" void kernel_launch(void* const* d_in, const int* in_sizes, int n_in,
                              void* d_out, int out_size)
{
    const float* hidden     = (const float*)d_in[0];
    const float* in_proj_w  = (const float*)d_in[1];
    const float* conv_w     = (const float*)d_in[2];
    const float* conv_b     = (const float*)d_in[3];
    const float* x_proj_w   = (const float*)d_in[4];
    const float* dt_proj_w  = (const float*)d_in[5];
    const float* dt_proj_b  = (const float*)d_in[6];
    const float* A_log      = (const float*)d_in[7];
    const float* D_skip     = (const float*)d_in[8];
    const float* out_proj_w = (const float*)d_in[9];
    float* out = (float*)d_out;

    cudaFuncSetAttribute(gemm_f16<0>,
                         cudaFuncAttributeMaxDynamicSharedMemorySize, GEMM_SMEM);
    cudaFuncSetAttribute(gemm_f16<1>,
                         cudaFuncAttributeMaxDynamicSharedMemorySize, GEMM_SMEM);

    float *xz, *xdbl, *part, *delta;
    __half *xch, *dth, *yh, *hh, *w1h, *w3h, *w4h, *w6h;
    cudaGetSymbolAddress((void**)&xz,    g_xz);
    cudaGetSymbolAddress((void**)&xdbl,  g_xdbl);
    cudaGetSymbolAddress((void**)&part,  g_part);
    cudaGetSymbolAddress((void**)&delta, g_delta);
    cudaGetSymbolAddress((void**)&xch,   g_xch);
    cudaGetSymbolAddress((void**)&dth,   g_dth);
    cudaGetSymbolAddress((void**)&yh,    g_yh);
    cudaGetSymbolAddress((void**)&hh,    g_hh);
    cudaGetSymbolAddress((void**)&w1h,   g_w1h);
    cudaGetSymbolAddress((void**)&w3h,   g_w3h);
    cudaGetSymbolAddress((void**)&w4h,   g_w4h);
    cudaGetSymbolAddress((void**)&w6h,   g_w6h);

    // 0) conversions needed by gemm1 (gemm1 stays at launch index 3 for ncu)
    cvt_kernel<<<(2 * D_INNER * D_MODEL / 4 + 255) / 256, 256>>>(
        in_proj_w, w1h, 2 * D_INNER * D_MODEL / 4);
    cvt_kernel<<<(D_MODEL * D_INNER / 4 + 255) / 256, 256>>>(
        out_proj_w, w6h, D_MODEL * D_INNER / 4);
    cvt_kernel<<<(BL * D_MODEL / 4 + 255) / 256, 256>>>(
        hidden, hh, BL * D_MODEL / 4);

    // 1) xz = hidden @ in_proj_w^T   (2048 x 4096 x 1024)
    gemm_f16<0><<<dim3(4096 / 128, BL / 128, 1), 256, GEMM_SMEM>>>(
        hh, D_MODEL, w1h, D_MODEL, xz, 2 * D_INNER,
        BL, 2 * D_INNER, D_MODEL, nullptr);

    cvt_kernel<<<(XPROJ * D_INNER / 4 + 255) / 256, 256>>>(
        x_proj_w, w3h, XPROJ * D_INNER / 4);
    cvt_kernel<<<(D_INNER * DT_RANK / 4 + 255) / 256, 256>>>(
        dt_proj_w, w4h, D_INNER * DT_RANK / 4);

    // 2) depthwise conv + SiLU -> xc (+ fp16 copy)
    conv_silu_kernel<<<(BL * D_INNER + 255) / 256, 256>>>(conv_w, conv_b);

    // 3) x_dbl = xc @ x_proj_w^T    (2048 x 96 x 2048), split-K=8 + reduce
    gemm_f16<0><<<dim3(1, BL / 128, KSPLIT), 256, GEMM_SMEM>>>(
        xch, D_INNER, w3h, D_INNER, part, XPROJ,
        BL, XPROJ, D_INNER / KSPLIT, nullptr);
    reduce_part_kernel<<<(BL * XPROJ + 255) / 256, 256>>>();

    // 4) delta = softplus(dt_lr @ dt_proj_w^T + dt_b)  (2048 x 2048 x 64)
    gemm_f16<1><<<dim3(D_INNER / 128, BL / 128, 1), 256, GEMM_SMEM>>>(
        dth, DT_RANK, w4h, DT_RANK, delta, D_INNER,
        BL, D_INNER, DT_RANK, dt_proj_b);

    // 5) selective scan + gating -> y (fp16)
    scan_kernel<<<dim3(D_INNER / 32, BATCH), 512>>>(A_log, D_skip);

    // 6) out = y @ out_proj_w^T     (2048 x 1024 x 2048)
    gemm_f16<0><<<dim3(D_MODEL / 128, BL / 128, 1), 256, GEMM_SMEM>>>(
        yh, D_INNER, w6h, D_INNER, out, D_MODEL,
        BL, D_MODEL, D_INNER, nullptr);
}

// round 6
// speedup vs baseline: 4.1218x; 1.0845x over previous
#include <cuda_runtime.h>
#include <cuda_fp16.h>
#include <math.h>
#include <stdint.h>

#define D_MODEL 1024
#define D_INNER 2048
#define D_STATE 16
#define D_CONV  4
#define DT_RANK 64
#define BATCH   2
#define SEQLEN  1024
#define BL      (BATCH * SEQLEN)          // 2048 rows
#define XPROJ   (DT_RANK + 2 * D_STATE)   // 96
#define KSPLIT  8
#define PCHUNK  4                          // parallel scan chunks
#define CHLEN   (SEQLEN / PCHUNK)          // 256 steps per chunk

// ---------------- scratch (static device globals; no allocs allowed) -------
__device__ __align__(16) float  g_xz  [(size_t)BL * 2 * D_INNER];   // 32 MB
__device__ __align__(16) float  g_xc  [(size_t)BL * D_INNER];       // 16 MB
__device__ __align__(16) __half g_xch [(size_t)BL * D_INNER];
__device__ __align__(16) float  g_xdbl[(size_t)BL * XPROJ];
__device__ __align__(16) float  g_part[(size_t)KSPLIT * BL * XPROJ];
__device__ __align__(16) __half g_dth [(size_t)BL * DT_RANK];
__device__ __align__(16) float  g_delta[(size_t)BL * D_INNER];      // 16 MB
__device__ __align__(16) __half g_yh  [(size_t)BL * D_INNER];
__device__ __align__(16) __half g_hh  [(size_t)BL * D_MODEL];
__device__ __align__(16) __half g_w1h [(size_t)2 * D_INNER * D_MODEL];
__device__ __align__(16) __half g_w3h [(size_t)XPROJ * D_INNER];
__device__ __align__(16) __half g_w4h [(size_t)D_INNER * DT_RANK];
__device__ __align__(16) __half g_w6h [(size_t)D_MODEL * D_INNER];
// scan chunk summaries: [b][chunk][d][n]
__device__ __align__(16) float  g_sloc  [(size_t)BATCH * PCHUNK * D_INNER * D_STATE];
__device__ __align__(16) float  g_ddec  [(size_t)BATCH * PCHUNK * D_INNER * D_STATE];
__device__ __align__(16) float  g_sstart[(size_t)BATCH * PCHUNK * D_INNER * D_STATE];

// ---------------- tiny PTX helpers -----------------------------------------
__device__ __forceinline__ uint32_t smem_u32(const void* p) {
    uint32_t a;
    asm("{ .reg .u64 t; cvta.to.shared.u64 t, %1; cvt.u32.u64 %0, t; }"
        : "=r"(a) : "l"(p));
    return a;
}
__device__ __forceinline__ uint32_t sw128(uint32_t off) {
    return off ^ ((off >> 3) & 0x70);
}
__device__ __forceinline__ void cpa16(uint32_t dst, const void* src, bool valid) {
    int sz = valid ? 16 : 0;
    asm volatile("cp.async.cg.shared.global [%0], [%1], 16, %2;"
                 :: "r"(dst), "l"(src), "r"(sz));
}
__device__ __forceinline__ void cpa16ca(uint32_t dst, const void* src) {
    asm volatile("cp.async.ca.shared.global [%0], [%1], 16;"
                 :: "r"(dst), "l"(src));
}
__device__ __forceinline__ void ldsm4(uint32_t* r, uint32_t addr) {
    asm volatile("ldmatrix.sync.aligned.m8n8.x4.shared.b16 {%0,%1,%2,%3}, [%4];"
                 : "=r"(r[0]), "=r"(r[1]), "=r"(r[2]), "=r"(r[3]) : "r"(addr));
}
__device__ __forceinline__ void mma_f16(float* d, const uint32_t* a,
                                        uint32_t b0, uint32_t b1) {
    asm volatile(
        "mma.sync.aligned.m16n8k16.row.col.f32.f16.f16.f32 "
        "{%0,%1,%2,%3}, {%4,%5,%6,%7}, {%8,%9}, {%0,%1,%2,%3};"
        : "+f"(d[0]), "+f"(d[1]), "+f"(d[2]), "+f"(d[3])
        : "r"(a[0]), "r"(a[1]), "r"(a[2]), "r"(a[3]), "r"(b0), "r"(b1));
}

// ---------------- fused fp32 -> fp16 conversion (all 5 tensors) -------------
__global__ void cvt_all_kernel(const float* __restrict__ w1,
                               const float* __restrict__ w6,
                               const float* __restrict__ hid,
                               const float* __restrict__ w3,
                               const float* __restrict__ w4)
{
    const int N1 = 2 * D_INNER * D_MODEL / 4;
    const int N6 = D_MODEL * D_INNER / 4;
    const int NH = BL * D_MODEL / 4;
    const int N3 = XPROJ * D_INNER / 4;
    const int N4 = D_INNER * DT_RANK / 4;

    int j = blockIdx.x * blockDim.x + threadIdx.x;
    const float* src; __half* dst;
    if (j < N1)                      { src = w1;  dst = g_w1h; }
    else if ((j -= N1) < N6)         { src = w6;  dst = g_w6h; }
    else if ((j -= N6) < NH)         { src = hid; dst = g_hh;  }
    else if ((j -= NH) < N3)         { src = w3;  dst = g_w3h; }
    else if ((j -= N3) < N4)         { src = w4;  dst = g_w4h; }
    else return;

    float4 v = ((const float4*)src)[j];
    __half2 a = __floats2half2_rn(v.x, v.y);
    __half2 b = __floats2half2_rn(v.z, v.w);
    ((uint2*)dst)[j] = make_uint2(*(uint32_t*)&a, *(uint32_t*)&b);
}

// ---------------- HMMA fp16 GEMM -------------------------------------------
#define KC 64
#define TILE_B   (128 * 128)
#define STAGE_B  (2 * TILE_B)
#define NSTAGE   3
#define GEMM_SMEM (NSTAGE * STAGE_B + 1024)

template <int EPI>
__global__ __launch_bounds__(256, 2)
void gemm_f16(const __half* __restrict__ A, int lda,
              const __half* __restrict__ B, int ldb,
              float* __restrict__ C, int ldc,
              int M, int N, int Kslice,
              const float* __restrict__ bias)
{
    extern __shared__ __align__(16) char dyns[];

    const int tid  = threadIdx.x;
    const int wid  = tid >> 5;
    const int lane = tid & 31;
    const int row0 = blockIdx.y * 128;
    const int col0 = blockIdx.x * 128;
    const int kBeg = blockIdx.z * Kslice;
    float* Cz = C + (size_t)blockIdx.z * (size_t)M * (size_t)ldc;
    const int nB = min(128, N - col0);
    const int chunks = Kslice / KC;

    const int warp_m = wid & 3;
    const int warp_n = wid >> 2;

    uint32_t sbase = (smem_u32(dyns) + 1023u) & ~1023u;

    float acc[2][8][4];
#pragma unroll
    for (int i = 0; i < 2; i++)
#pragma unroll
        for (int j = 0; j < 8; j++)
#pragma unroll
            for (int k = 0; k < 4; k++) acc[i][j][k] = 0.f;

    auto load_chunk = [&](int c) {
        uint32_t st = sbase + (uint32_t)(c % NSTAGE) * STAGE_B;
        int kcol = kBeg + c * KC;
        int seg = tid & 7;
#pragma unroll
        for (int j = 0; j < 4; j++) {
            int row = (tid >> 3) + j * 32;
            uint32_t so = sw128((uint32_t)(row * 128 + seg * 16));
            const __half* pa = A + (size_t)(row0 + row) * lda + kcol + seg * 8;
            cpa16(st + so, pa, true);
            bool bv = row < nB;
            int  br = bv ? row : 0;
            const __half* pb = B + (size_t)(col0 + br) * ldb + kcol + seg * 8;
            cpa16(st + TILE_B + so, pb, bv);
        }
        asm volatile("cp.async.commit_group;" ::: "memory");
    };

#pragma unroll
    for (int p = 0; p < NSTAGE - 1; p++)
        if (p < chunks) load_chunk(p);

    const int lrow  = lane & 15;
    const int lhalf = lane >> 4;

    // hoisted swizzled fragment base offsets (sw128(x|kb) == sw128(x)^kb here)
    uint32_t swa[2], swb[4];
#pragma unroll
    for (int mf = 0; mf < 2; mf++)
        swa[mf] = sw128((uint32_t)((warp_m * 32 + mf * 16 + lrow) * 128));
#pragma unroll
    for (int nf = 0; nf < 4; nf++)
        swb[nf] = sw128((uint32_t)((warp_n * 64 + nf * 16 + lrow) * 128)) + TILE_B;

    for (int c = 0; c < chunks; c++) {
        int pend = chunks - 1 - c;
        if (pend > NSTAGE - 2) pend = NSTAGE - 2;
        if (pend == 1) asm volatile("cp.async.wait_group 1;" ::: "memory");
        else           asm volatile("cp.async.wait_group 0;" ::: "memory");
        __syncthreads();

        if (c + NSTAGE - 1 < chunks) load_chunk(c + NSTAGE - 1);

        uint32_t st = sbase + (uint32_t)(c % NSTAGE) * STAGE_B;
        uint32_t aAddr0 = st + swa[0], aAddr1 = st + swa[1];
        uint32_t bAddr0 = st + swb[0], bAddr1 = st + swb[1];
        uint32_t bAddr2 = st + swb[2], bAddr3 = st + swb[3];

#pragma unroll
        for (int ks = 0; ks < KC / 16; ks++) {
            const uint32_t kb = (uint32_t)(ks * 32 + lhalf * 16);

            uint32_t af[2][4];
            ldsm4(af[0], aAddr0 ^ kb);
            ldsm4(af[1], aAddr1 ^ kb);
            uint32_t bf[4][4];
            ldsm4(bf[0], bAddr0 ^ kb);
            ldsm4(bf[1], bAddr1 ^ kb);
            ldsm4(bf[2], bAddr2 ^ kb);
            ldsm4(bf[3], bAddr3 ^ kb);
#pragma unroll
            for (int mf = 0; mf < 2; mf++) {
#pragma unroll
                for (int nf = 0; nf < 4; nf++) {
                    mma_f16(acc[mf][2 * nf],     af[mf], bf[nf][0], bf[nf][2]);
                    mma_f16(acc[mf][2 * nf + 1], af[mf], bf[nf][1], bf[nf][3]);
                }
            }
        }
        __syncthreads();
    }

#pragma unroll
    for (int mf = 0; mf < 2; mf++) {
        int r = row0 + warp_m * 32 + mf * 16 + (lane >> 2);
#pragma unroll
        for (int j = 0; j < 8; j++) {
            int ccol = col0 + warp_n * 64 + j * 8 + (lane & 3) * 2;
            if (ccol < N) {
                float v0 = acc[mf][j][0], v1 = acc[mf][j][1];
                float v2 = acc[mf][j][2], v3 = acc[mf][j][3];
                if (EPI == 1) {
                    v0 += bias[ccol];     v1 += bias[ccol + 1];
                    v2 += bias[ccol];     v3 += bias[ccol + 1];
                    v0 = (v0 > 20.f) ? v0 : log1pf(__expf(v0));
                    v1 = (v1 > 20.f) ? v1 : log1pf(__expf(v1));
                    v2 = (v2 > 20.f) ? v2 : log1pf(__expf(v2));
                    v3 = (v3 > 20.f) ? v3 : log1pf(__expf(v3));
                }
                *(float2*)&Cz[(size_t)r * ldc + ccol]       = make_float2(v0, v1);
                *(float2*)&Cz[(size_t)(r + 8) * ldc + ccol] = make_float2(v2, v3);
            }
        }
    }
}

// ---------------- reduce split-K partials + dt_lr fp16 ----------------------
__global__ void reduce_part_kernel()
{
    int i = blockIdx.x * blockDim.x + threadIdx.x;
    if (i < BL * XPROJ) {
        float s = 0.f;
#pragma unroll
        for (int p = 0; p < KSPLIT; p++)
            s += g_part[(size_t)p * BL * XPROJ + i];
        g_xdbl[i] = s;
        int col = i % XPROJ;
        if (col < DT_RANK) {
            int row = i / XPROJ;
            g_dth[(size_t)row * DT_RANK + col] = __float2half_rn(s);
        }
    }
}

// ---------------- depthwise causal conv + bias + SiLU (+ fp16 copy) --------
__global__ void conv_silu_kernel(const float* __restrict__ w,
                                 const float* __restrict__ bias)
{
    int idx = blockIdx.x * blockDim.x + threadIdx.x;
    if (idx >= BL * D_INNER) return;
    int d  = idx % D_INNER;
    int bl = idx / D_INNER;
    int l  = bl % SEQLEN;

    float acc = bias[d];
#pragma unroll
    for (int k = 0; k < D_CONV; k++) {
        int lk = l - (D_CONV - 1) + k;
        if (lk >= 0)
            acc += w[d * D_CONV + k] *
                   g_xz[(size_t)(bl - (D_CONV - 1 - k)) * (2 * D_INNER) + d];
    }
    float sg = 1.f / (1.f + __expf(-acc));
    float v = acc * sg;
    g_xc[idx]  = v;
    g_xch[idx] = __float2half_rn(v);
}

// ---------------- chunked selective scan ------------------------------------
// PHASE 0 (A): per chunk, local scan from s=0; emit s_loc and decay=exp(An*sumdl).
// PHASE 1 (C): per chunk, scan from g_sstart; emit gated y (fp16).
// grid (D_INNER/32, BATCH, PCHUNK); 512 thr = 32 channels x 16 states.
#define TL 64
template <int PHASE>
__global__ __launch_bounds__(512)
void scan_phase(const float* __restrict__ A_log,
                const float* __restrict__ D_skip)
{
    __shared__ float sD[2][TL][32];
    __shared__ float sU[2][TL][32];
    __shared__ float sB[2][TL][16];
    __shared__ float sC[2][TL][16];
    __shared__ float sY[TL][32];

    const int b    = blockIdx.y;
    const int ck   = blockIdx.z;
    const int d0   = blockIdx.x * 32;
    const int tid  = threadIdx.x;
    const int dc   = tid >> 4;
    const int n    = tid & 15;
    const int d    = d0 + dc;
    const int lbase = ck * CHLEN;

    const float An = -__expf(A_log[d * D_STATE + n]);
    const size_t sumIdx = ((size_t)(b * PCHUNK + ck) * D_INNER + d) * D_STATE + n;

    float s = 0.f;
    if (PHASE == 1) s = g_sstart[sumIdx];
    float sumdl = 0.f;
    const float Dskip = D_skip[d0 + (tid & 31)];

    auto stage = [&](int j) {
        int buf = j & 1;
        int l0 = lbase + j * TL;
        {
            int t = tid >> 3, seg = tid & 7;
            size_t row = (size_t)(b * SEQLEN + l0 + t);
            cpa16ca(smem_u32(&sD[buf][t][seg * 4]),
                    &g_delta[row * D_INNER + d0 + seg * 4]);
            cpa16ca(smem_u32(&sU[buf][t][seg * 4]),
                    &g_xc[row * D_INNER + d0 + seg * 4]);
        }
        if (tid < 256) {
            int t = tid >> 2, seg = tid & 3;
            size_t row = (size_t)(b * SEQLEN + l0 + t);
            cpa16ca(smem_u32(&sB[buf][t][seg * 4]),
                    &g_xdbl[row * XPROJ + DT_RANK + seg * 4]);
        } else if (PHASE == 1) {
            int t2 = tid - 256;
            int t = t2 >> 2, seg = t2 & 3;
            size_t row = (size_t)(b * SEQLEN + l0 + t);
            cpa16ca(smem_u32(&sC[buf][t][seg * 4]),
                    &g_xdbl[row * XPROJ + DT_RANK + D_STATE + seg * 4]);
        }
        asm volatile("cp.async.commit_group;" ::: "memory");
    };

    const int NJ = CHLEN / TL;   // 4 sub-chunks
    stage(0);

    for (int j = 0; j < NJ; j++) {
        if (j + 1 < NJ) {
            stage(j + 1);
            asm volatile("cp.async.wait_group 1;" ::: "memory");
        } else {
            asm volatile("cp.async.wait_group 0;" ::: "memory");
        }
        __syncthreads();

        const int buf = j & 1;
#pragma unroll 4
        for (int t = 0; t < TL; t++) {
            float dl = sD[buf][t][dc];
            float u  = sU[buf][t][dc];
            float dA = __expf(dl * An);
            s = fmaf(s, dA, (dl * u) * sB[buf][t][n]);
            if (PHASE == 0) {
                sumdl += dl;
            } else {
                float v = s * sC[buf][t][n];
                v += __shfl_xor_sync(0xffffffffu, v, 8);
                v += __shfl_xor_sync(0xffffffffu, v, 4);
                v += __shfl_xor_sync(0xffffffffu, v, 2);
                v += __shfl_xor_sync(0xffffffffu, v, 1);
                if (n == 0) sY[t][dc] = v;
            }
        }

        if (PHASE == 1) {
            __syncthreads();
            int l0 = lbase + j * TL;
            for (int i = tid; i < TL * 32; i += 512) {
                int t = i >> 5, ch = i & 31;
                size_t row = (size_t)(b * SEQLEN + l0 + t);
                float u  = sU[buf][t][ch];
                float yv = sY[t][ch] + u * Dskip;
                float z  = g_xz[row * (2 * D_INNER) + D_INNER + d0 + ch];
                yv *= z / (1.f + __expf(-z));
                g_yh[row * D_INNER + d0 + ch] = __float2half_rn(yv);
            }
        }
        __syncthreads();
    }

    if (PHASE == 0) {
        g_sloc[sumIdx] = s;
        g_ddec[sumIdx] = __expf(An * sumdl);
    }
}

// ---------------- serial combine across chunks ------------------------------
__global__ void scan_combine_kernel()
{
    int i = blockIdx.x * blockDim.x + threadIdx.x;
    if (i >= BATCH * D_INNER * D_STATE) return;
    int n = i & 15;
    int d = (i >> 4) & (D_INNER - 1);
    int b = i >> 15;                       // 4 + 11 bits
    float s = 0.f;
#pragma unroll
    for (int c = 0; c < PCHUNK; c++) {
        size_t idx = ((size_t)(b * PCHUNK + c) * D_INNER + d) * D_STATE + n;
        g_sstart[idx] = s;
        s = s * g_ddec[idx] + g_sloc[idx];
    }
}

// ---------------- launcher --------------------------------------------------
extern "C" void kernel_launch(void* const* d_in, const int* in_sizes, int n_in,
                              void* d_out, int out_size)
{
    const float* hidden     = (const float*)d_in[0];
    const float* in_proj_w  = (const float*)d_in[1];
    const float* conv_w     = (const float*)d_in[2];
    const float* conv_b     = (const float*)d_in[3];
    const float* x_proj_w   = (const float*)d_in[4];
    const float* dt_proj_w  = (const float*)d_in[5];
    const float* dt_proj_b  = (const float*)d_in[6];
    const float* A_log      = (const float*)d_in[7];
    const float* D_skip     = (const float*)d_in[8];
    const float* out_proj_w = (const float*)d_in[9];
    float* out = (float*)d_out;

    cudaFuncSetAttribute(gemm_f16<0>,
                         cudaFuncAttributeMaxDynamicSharedMemorySize, GEMM_SMEM);
    cudaFuncSetAttribute(gemm_f16<1>,
                         cudaFuncAttributeMaxDynamicSharedMemorySize, GEMM_SMEM);

    float *xz, *xdbl, *part, *delta;
    __half *xch, *dth, *yh, *hh, *w1h, *w3h, *w4h, *w6h;
    cudaGetSymbolAddress((void**)&xz,    g_xz);
    cudaGetSymbolAddress((void**)&xdbl,  g_xdbl);
    cudaGetSymbolAddress((void**)&part,  g_part);
    cudaGetSymbolAddress((void**)&delta, g_delta);
    cudaGetSymbolAddress((void**)&xch,   g_xch);
    cudaGetSymbolAddress((void**)&dth,   g_dth);
    cudaGetSymbolAddress((void**)&yh,    g_yh);
    cudaGetSymbolAddress((void**)&hh,    g_hh);
    cudaGetSymbolAddress((void**)&w1h,   g_w1h);
    cudaGetSymbolAddress((void**)&w3h,   g_w3h);
    cudaGetSymbolAddress((void**)&w4h,   g_w4h);
    cudaGetSymbolAddress((void**)&w6h,   g_w6h);

    // 0) all fp32->fp16 conversions in one launch
    {
        int total = (2 * D_INNER * D_MODEL + D_MODEL * D_INNER + BL * D_MODEL +
                     XPROJ * D_INNER + D_INNER * DT_RANK) / 4;
        cvt_all_kernel<<<(total + 255) / 256, 256>>>(in_proj_w, out_proj_w,
                                                     hidden, x_proj_w, dt_proj_w);
    }

    // 1) xz = hidden @ in_proj_w^T   (2048 x 4096 x 1024)
    gemm_f16<0><<<dim3(4096 / 128, BL / 128, 1), 256, GEMM_SMEM>>>(
        hh, D_MODEL, w1h, D_MODEL, xz, 2 * D_INNER,
        BL, 2 * D_INNER, D_MODEL, nullptr);

    // 2) depthwise conv + SiLU -> xc (+ fp16 copy)
    conv_silu_kernel<<<(BL * D_INNER + 255) / 256, 256>>>(conv_w, conv_b);

    // 3) x_dbl = xc @ x_proj_w^T    (2048 x 96 x 2048), split-K=8 + reduce
    gemm_f16<0><<<dim3(1, BL / 128, KSPLIT), 256, GEMM_SMEM>>>(
        xch, D_INNER, w3h, D_INNER, part, XPROJ,
        BL, XPROJ, D_INNER / KSPLIT, nullptr);
    reduce_part_kernel<<<(BL * XPROJ + 255) / 256, 256>>>();

    // 4) delta = softplus(dt_lr @ dt_proj_w^T + dt_b)  (2048 x 2048 x 64)
    gemm_f16<1><<<dim3(D_INNER / 128, BL / 128, 1), 256, GEMM_SMEM>>>(
        dth, DT_RANK, w4h, DT_RANK, delta, D_INNER,
        BL, D_INNER, DT_RANK, dt_proj_b);

    // 5) chunked selective scan: local pass, combine, final pass
    scan_phase<0><<<dim3(D_INNER / 32, BATCH, PCHUNK), 512>>>(A_log, D_skip);
    scan_combine_kernel<<<(BATCH * D_INNER * D_STATE + 255) / 256, 256>>>();
    scan_phase<1><<<dim3(D_INNER / 32, BATCH, PCHUNK), 512>>>(A_log, D_skip);

    // 6) out = y @ out_proj_w^T     (2048 x 1024 x 2048)
    gemm_f16<0><<<dim3(D_MODEL / 128, BL / 128, 1), 256, GEMM_SMEM>>>(
        yh, D_INNER, w6h, D_INNER, out, D_MODEL,
        BL, D_MODEL, D_INNER, nullptr);
}